// round 9
// baseline (speedup 1.0000x reference)
#include <cuda_runtime.h>
#include <cuda_fp16.h>
#include <math.h>
#include <stdint.h>

#define NDEPTH 25
#define DT     (1.0f/25.0f)
#define NBATCH 262144
#define TILE_M 128
#define NTHREADS 256

// ---------------- smem float-index offsets (per-CTA ~59KB, 3 CTAs/SM) ----------------
#define F_NOISE  0            // 25x64
#define F_BD     1600         // 64
#define F_BDR    1664         // 64
#define F_B1     1728         // 104
#define F_W2     1832         // 104
#define F_B2     1936         // 1 (pad 4)
#define F_BHI    1940         // drift hi: 32 groups x 32 lanes x uint2 (8KB)
#define F_BLO    3988         // drift lo: 8KB
#define F_STAGE  6036         // 128 rows x pitch 68
#define ST_PITCH 68
#define F_TOTAL  (F_STAGE + 128*ST_PITCH)
#define SMEM_BYTES (F_TOTAL*4)        // 58960 B

__device__ float g_noise[NDEPTH*64];
// one-time fragment tables in global (built by prep_kernel, read once per CTA)
__device__ uint2 g_tWDhi[32*32], g_tWDlo[32*32];   // W_down,  g = kt*8 + nt
__device__ uint2 g_tDRhi[32*32], g_tDRlo[32*32];   // W_drift, g = kt*8 + nt
__device__ uint2 g_tW1hi[52*32], g_tW1lo[52*32];   // W1,      g = kt*13 + nt

// ---------------- fp16 pack/split helpers ----------------
__device__ __forceinline__ uint32_t pkh(float e0, float e1) {
    uint32_t r;
    asm("cvt.rn.f16x2.f32 %0, %1, %2;" : "=r"(r) : "f"(e1), "f"(e0));
    return r;
}
__device__ __forceinline__ float h_lo(uint32_t p) {
    __half2 h = *(__half2*)&p; return __low2float(h);
}
__device__ __forceinline__ float h_hi(uint32_t p) {
    __half2 h = *(__half2*)&p; return __high2float(h);
}
__device__ __forceinline__ void split2(float v0, float v1, uint32_t& hi, uint32_t& lo) {
    hi = pkh(v0, v1);
    lo = pkh(v0 - h_lo(hi), v1 - h_hi(hi));
}

__device__ __forceinline__ void mma16816(float* c,
                                         uint32_t a0, uint32_t a1, uint32_t a2, uint32_t a3,
                                         uint32_t b0, uint32_t b1) {
    asm volatile(
        "mma.sync.aligned.m16n8k16.row.col.f32.f16.f16.f32 "
        "{%0,%1,%2,%3}, {%4,%5,%6,%7}, {%8,%9}, {%0,%1,%2,%3};"
        : "+f"(c[0]), "+f"(c[1]), "+f"(c[2]), "+f"(c[3])
        : "r"(a0), "r"(a1), "r"(a2), "r"(a3), "r"(b0), "r"(b1));
}

// ---------------- Lévy noise prologue (fp64) ----------------
__global__ void noise_kernel(const float* __restrict__ u_raw,
                             const float* __restrict__ w_raw) {
    int i = blockIdx.x * blockDim.x + threadIdx.x;
    if (i >= NDEPTH * 64) return;
    double u = (double)u_raw[i];
    double w = (double)w_raw[i];
    double U = 3.14159265358979323846 * (u - 0.5);
    double wc = w; if (wc < 1e-12) wc = 1e-12; if (wc > 1.0) wc = 1.0;
    double Wv = -log(wc); if (Wv < 1e-12) Wv = 1e-12;
    const double inv_a = 1.0 / 1.8;
    double X = (sin(1.8 * U) / pow(cos(U), inv_a))
             * pow(cos(U - 1.8 * U) / Wv, (1.0 - 1.8) * inv_a);
    double n = 0.1 * X;
    if (n >  10.0) n =  10.0;
    if (n < -10.0) n = -10.0;
    g_noise[i] = (float)n;
}

// ---------------- fragment-table prep (one-time) ----------------
__global__ void prep_kernel(const float* __restrict__ W_down,
                            const float* __restrict__ W_drift,
                            const float* __restrict__ W1) {
    int idx = blockIdx.x * blockDim.x + threadIdx.x;
    int lane = idx & 31, g = idx >> 5;
    int quad = lane >> 2, qt = lane & 3;
    if (idx < 1024) {
        int nt = g & 7, kt = g >> 3;
        int n = quad + 8 * nt;
        int k = 16 * kt + 2 * qt;
        uint32_t h0, l0, h1, l1;
        split2(W_down[k * 64 + n],       W_down[(k + 1) * 64 + n], h0, l0);
        split2(W_down[(k + 8) * 64 + n], W_down[(k + 9) * 64 + n], h1, l1);
        g_tWDhi[idx] = make_uint2(h0, h1);
        g_tWDlo[idx] = make_uint2(l0, l1);
        split2(W_drift[k * 64 + n],       W_drift[(k + 1) * 64 + n], h0, l0);
        split2(W_drift[(k + 8) * 64 + n], W_drift[(k + 9) * 64 + n], h1, l1);
        g_tDRhi[idx] = make_uint2(h0, h1);
        g_tDRlo[idx] = make_uint2(l0, l1);
    }
    if (idx < 1664) {
        int nt = g % 13, kt = g / 13;
        int n = quad + 8 * nt;
        int k = 16 * kt + 2 * qt;
        float w0 = (n < 100) ? W1[k * 100 + n]       : 0.0f;
        float w1 = (n < 100) ? W1[(k + 1) * 100 + n] : 0.0f;
        float w2 = (n < 100) ? W1[(k + 8) * 100 + n] : 0.0f;
        float w3 = (n < 100) ? W1[(k + 9) * 100 + n] : 0.0f;
        uint32_t h0, l0, h1, l1;
        split2(w0, w1, h0, l0);
        split2(w2, w3, h1, l1);
        g_tW1hi[idx] = make_uint2(h0, h1);
        g_tW1lo[idx] = make_uint2(l0, l1);
    }
}

// ---------------- main: 8 warps/CTA, 3 CTAs/SM, warp owns rows 16w..16w+15 ----------------
__global__ void __launch_bounds__(NTHREADS, 3)
sdenet_mma(const float* __restrict__ x,
           const float* __restrict__ b_down,
           const float* __restrict__ b_drift,
           const float* __restrict__ b1,
           const float* __restrict__ W2,
           const float* __restrict__ b2,
           float* __restrict__ out) {
    extern __shared__ float sm[];
    const int tid  = threadIdx.x;
    const int wid  = tid >> 5;
    const int lane = tid & 31;
    const int quad = lane >> 2;
    const int qt   = lane & 3;

    // ---- cooperative loads ----
    for (int i = tid; i < NDEPTH * 64; i += NTHREADS) sm[F_NOISE + i] = g_noise[i];
    if (tid < 64)  { sm[F_BD + tid] = b_down[tid]; sm[F_BDR + tid] = b_drift[tid]; }
    if (tid < 104) {
        sm[F_B1 + tid] = (tid < 100) ? b1[tid] : 0.0f;
        sm[F_W2 + tid] = (tid < 100) ? W2[tid] : 0.0f;
    }
    if (tid == 0) sm[F_B2] = b2[0];
    // drift tables global -> smem (coalesced, 4 uint2 per thread per table)
    {
        uint2* th = (uint2*)&sm[F_BHI];
        uint2* tl = (uint2*)&sm[F_BLO];
        for (int i = tid; i < 1024; i += NTHREADS) {
            th[i] = g_tDRhi[i];
            tl[i] = g_tDRlo[i];
        }
    }
    // x tile -> stage (coalesced)
    const float* xb = x + (size_t)blockIdx.x * (TILE_M * 64);
    for (int i = 4 * tid; i < TILE_M * 64; i += 4 * NTHREADS) {
        float4 v = *(const float4*)(xb + i);
        int r = i >> 6, c = i & 63;
        *(float4*)&sm[F_STAGE + r * ST_PITCH + c] = v;
    }
    __syncthreads();

    const int row0 = 16 * wid + quad;

    // ---- A fragments of x (hi/lo) ----
    uint32_t ah[16], al[16];
#pragma unroll
    for (int kt = 0; kt < 4; kt++) {
        int k0 = 16 * kt + 2 * qt;
        const float* r0p = &sm[F_STAGE + row0 * ST_PITCH];
        const float* r1p = &sm[F_STAGE + (row0 + 8) * ST_PITCH];
        split2(r0p[k0],     r0p[k0 + 1], ah[4*kt + 0], al[4*kt + 0]);
        split2(r1p[k0],     r1p[k0 + 1], ah[4*kt + 1], al[4*kt + 1]);
        split2(r0p[k0 + 8], r0p[k0 + 9], ah[4*kt + 2], al[4*kt + 2]);
        split2(r1p[k0 + 8], r1p[k0 + 9], ah[4*kt + 3], al[4*kt + 3]);
    }

    // ---- GEMM1: s = x @ W_down + b_down (3-term fp16; B frags from global table) ----
    float d[8][4];
#pragma unroll
    for (int nt = 0; nt < 8; nt++) {
        int c0 = 8 * nt + 2 * qt;
        float c[4] = { sm[F_BD + c0], sm[F_BD + c0 + 1], sm[F_BD + c0], sm[F_BD + c0 + 1] };
#pragma unroll
        for (int kt = 0; kt < 4; kt++) {
            uint2 bh = g_tWDhi[(kt * 8 + nt) * 32 + lane];
            uint2 bl = g_tWDlo[(kt * 8 + nt) * 32 + lane];
            mma16816(c, ah[4*kt], ah[4*kt+1], ah[4*kt+2], ah[4*kt+3], bh.x, bh.y);
            mma16816(c, al[4*kt], al[4*kt+1], al[4*kt+2], al[4*kt+3], bh.x, bh.y);
            mma16816(c, ah[4*kt], ah[4*kt+1], ah[4*kt+2], ah[4*kt+3], bl.x, bl.y);
        }
        d[nt][0] = c[0]; d[nt][1] = c[1]; d[nt][2] = c[2]; d[nt][3] = c[3];
    }

    // rebuild A fragments from state (full split for MLP precision)
#pragma unroll
    for (int kt = 0; kt < 4; kt++) {
        split2(d[2*kt][0],   d[2*kt][1],   ah[4*kt + 0], al[4*kt + 0]);
        split2(d[2*kt][2],   d[2*kt][3],   ah[4*kt + 1], al[4*kt + 1]);
        split2(d[2*kt+1][0], d[2*kt+1][1], ah[4*kt + 2], al[4*kt + 2]);
        split2(d[2*kt+1][2], d[2*kt+1][3], ah[4*kt + 3], al[4*kt + 3]);
    }

    // ---- diffusion MLP (3-term fp16; B frags from global table) ----
    float p0 = 0.0f, p1 = 0.0f;
#pragma unroll
    for (int nt = 0; nt < 13; nt++) {
        float c[4] = {0.f, 0.f, 0.f, 0.f};
#pragma unroll
        for (int kt = 0; kt < 4; kt++) {
            uint2 bh = g_tW1hi[(kt * 13 + nt) * 32 + lane];
            uint2 bl = g_tW1lo[(kt * 13 + nt) * 32 + lane];
            mma16816(c, ah[4*kt], ah[4*kt+1], ah[4*kt+2], ah[4*kt+3], bh.x, bh.y);
            mma16816(c, al[4*kt], al[4*kt+1], al[4*kt+2], al[4*kt+3], bh.x, bh.y);
            mma16816(c, ah[4*kt], ah[4*kt+1], ah[4*kt+2], ah[4*kt+3], bl.x, bl.y);
        }
        int c0 = 8 * nt + 2 * qt;
        float w20 = sm[F_W2 + c0], w21 = sm[F_W2 + c0 + 1];
        float bb0 = sm[F_B1 + c0], bb1 = sm[F_B1 + c0 + 1];
        p0 += fmaxf(c[0] + bb0, 0.f) * w20 + fmaxf(c[1] + bb1, 0.f) * w21;
        p1 += fmaxf(c[2] + bb0, 0.f) * w20 + fmaxf(c[3] + bb1, 0.f) * w21;
    }
    p0 += __shfl_xor_sync(0xffffffffu, p0, 1);
    p0 += __shfl_xor_sync(0xffffffffu, p0, 2);
    p1 += __shfl_xor_sync(0xffffffffu, p1, 1);
    p1 += __shfl_xor_sync(0xffffffffu, p1, 2);
    const float dtpow = powf(DT, 1.0f / 1.8f);
    const float b2v = sm[F_B2];
    const float scale0 = 0.5f * dtpow / (1.0f + expf(-(p0 + b2v)));
    const float scale1 = 0.5f * dtpow / (1.0f + expf(-(p1 + b2v)));

    // ---- 25 drift steps: single-term A-hi x B-hi, TWO nt-passes of 4 (c[4][4] live) ----
    const uint2* tbh = (const uint2*)&sm[F_BHI] + lane;
    const uint2* tbl = (const uint2*)&sm[F_BLO] + lane;
    const float* bdrp = &sm[F_BDR + 2 * qt];
    const float* nzp  = &sm[F_NOISE + 2 * qt];
#pragma unroll 1
    for (int st = 0; st < NDEPTH; st++) {
        const float* nz = nzp + st * 64;
#pragma unroll
        for (int pass = 0; pass < 2; pass++) {
            const int nt0 = 4 * pass;
            float c[4][4];
#pragma unroll
            for (int j = 0; j < 4; j++) {
                float2 bb = *(const float2*)(bdrp + 8 * (nt0 + j));
                c[j][0] = bb.x; c[j][1] = bb.y; c[j][2] = bb.x; c[j][3] = bb.y;
            }
#pragma unroll
            for (int kt = 0; kt < 4; kt++) {
                uint2 b[4];
#pragma unroll
                for (int j = 0; j < 4; j++) b[j] = tbh[(kt * 8 + nt0 + j) * 32];
#pragma unroll
                for (int j = 0; j < 4; j++)
                    mma16816(c[j], ah[4*kt], ah[4*kt+1], ah[4*kt+2], ah[4*kt+3],
                             b[j].x, b[j].y);
            }
#pragma unroll
            for (int j = 0; j < 4; j++) {
                int nt = nt0 + j;
                float2 z = *(const float2*)(nz + 8 * nt);
                d[nt][0] = fmaf(d[nt][0], 1.0f + DT, fmaf(fmaxf(c[j][0], 0.f), DT, scale0 * z.x));
                d[nt][1] = fmaf(d[nt][1], 1.0f + DT, fmaf(fmaxf(c[j][1], 0.f), DT, scale0 * z.y));
                d[nt][2] = fmaf(d[nt][2], 1.0f + DT, fmaf(fmaxf(c[j][2], 0.f), DT, scale1 * z.x));
                d[nt][3] = fmaf(d[nt][3], 1.0f + DT, fmaf(fmaxf(c[j][3], 0.f), DT, scale1 * z.y));
            }
        }
        // A-hi rebuild: one cvt per fragment
#pragma unroll
        for (int kt = 0; kt < 4; kt++) {
            ah[4*kt + 0] = pkh(d[2*kt][0],   d[2*kt][1]);
            ah[4*kt + 1] = pkh(d[2*kt][2],   d[2*kt][3]);
            ah[4*kt + 2] = pkh(d[2*kt+1][0], d[2*kt+1][1]);
            ah[4*kt + 3] = pkh(d[2*kt+1][2], d[2*kt+1][3]);
        }
    }

    // ---- final drift_out GEMM: full precision (3-term, A fully split) ----
#pragma unroll
    for (int kt = 0; kt < 4; kt++) {
        split2(d[2*kt][0],   d[2*kt][1],   ah[4*kt + 0], al[4*kt + 0]);
        split2(d[2*kt][2],   d[2*kt][3],   ah[4*kt + 1], al[4*kt + 1]);
        split2(d[2*kt+1][0], d[2*kt+1][1], ah[4*kt + 2], al[4*kt + 2]);
        split2(d[2*kt+1][2], d[2*kt+1][3], ah[4*kt + 3], al[4*kt + 3]);
    }
#pragma unroll
    for (int nt = 0; nt < 8; nt++) {
        int c0 = 8 * nt + 2 * qt;
        float2 bb = *(const float2*)&sm[F_BDR + c0];
        float c[4] = { bb.x, bb.y, bb.x, bb.y };
#pragma unroll
        for (int kt = 0; kt < 4; kt++) {
            uint2 b = tbh[(kt * 8 + nt) * 32];
            uint2 l = tbl[(kt * 8 + nt) * 32];
            mma16816(c, ah[4*kt], ah[4*kt+1], ah[4*kt+2], ah[4*kt+3], b.x, b.y);
            mma16816(c, al[4*kt], al[4*kt+1], al[4*kt+2], al[4*kt+3], b.x, b.y);
            mma16816(c, ah[4*kt], ah[4*kt+1], ah[4*kt+2], ah[4*kt+3], l.x, l.y);
        }
        sm[F_STAGE + row0 * ST_PITCH + c0]           = fmaxf(c[0], 0.f) + d[nt][0];
        sm[F_STAGE + row0 * ST_PITCH + c0 + 1]       = fmaxf(c[1], 0.f) + d[nt][1];
        sm[F_STAGE + (row0 + 8) * ST_PITCH + c0]     = fmaxf(c[2], 0.f) + d[nt][2];
        sm[F_STAGE + (row0 + 8) * ST_PITCH + c0 + 1] = fmaxf(c[3], 0.f) + d[nt][3];
    }

    // ---- write drift_out (coalesced via stage) ----
    __syncthreads();
    float* o0 = out + (size_t)blockIdx.x * (TILE_M * 64);
    for (int i = 4 * tid; i < TILE_M * 64; i += 4 * NTHREADS) {
        int r = i >> 6, c = i & 63;
        *(float4*)(o0 + i) = *(const float4*)&sm[F_STAGE + r * ST_PITCH + c];
    }
    __syncthreads();

    // ---- stage + write final state ----
#pragma unroll
    for (int nt = 0; nt < 8; nt++) {
        int c0 = 8 * nt + 2 * qt;
        sm[F_STAGE + row0 * ST_PITCH + c0]           = d[nt][0];
        sm[F_STAGE + row0 * ST_PITCH + c0 + 1]       = d[nt][1];
        sm[F_STAGE + (row0 + 8) * ST_PITCH + c0]     = d[nt][2];
        sm[F_STAGE + (row0 + 8) * ST_PITCH + c0 + 1] = d[nt][3];
    }
    __syncthreads();
    float* o1 = out + (size_t)NBATCH * 64 + (size_t)blockIdx.x * (TILE_M * 64);
    for (int i = 4 * tid; i < TILE_M * 64; i += 4 * NTHREADS) {
        int r = i >> 6, c = i & 63;
        *(float4*)(o1 + i) = *(const float4*)&sm[F_STAGE + r * ST_PITCH + c];
    }
}

extern "C" void kernel_launch(void* const* d_in, const int* in_sizes, int n_in,
                              void* d_out, int out_size) {
    const float* x       = (const float*)d_in[0];
    const float* u_raw   = (const float*)d_in[1];
    const float* w_raw   = (const float*)d_in[2];
    const float* W_down  = (const float*)d_in[3];
    const float* b_down  = (const float*)d_in[4];
    const float* W_drift = (const float*)d_in[5];
    const float* b_drift = (const float*)d_in[6];
    const float* W1      = (const float*)d_in[7];
    const float* b1      = (const float*)d_in[8];
    const float* W2      = (const float*)d_in[9];
    const float* b2      = (const float*)d_in[10];
    float* out = (float*)d_out;

    noise_kernel<<<(NDEPTH * 64 + 255) / 256, 256>>>(u_raw, w_raw);
    prep_kernel<<<7, 256>>>(W_down, W_drift, W1);

    cudaFuncSetAttribute(sdenet_mma,
                         cudaFuncAttributeMaxDynamicSharedMemorySize, SMEM_BYTES);
    sdenet_mma<<<NBATCH / TILE_M, NTHREADS, SMEM_BYTES>>>(
        x, b_down, b_drift, b1, W2, b2, out);
}

// round 10
// speedup vs baseline: 1.3288x; 1.3288x over previous
#include <cuda_runtime.h>
#include <cuda_fp16.h>
#include <math.h>
#include <stdint.h>

#define NDEPTH 25
#define DT     (1.0f/25.0f)
#define NBATCH 262144
#define TILE_M 128
#define NTHREADS 256

// ---------------- smem float-index offsets (per-CTA ~59KB, 3 CTAs/SM) ----------------
#define F_NOISE  0            // 25x64
#define F_BD     1600         // 64
#define F_BDR    1664         // 64
#define F_B1     1728         // 104
#define F_W2     1832         // 104
#define F_B2     1936         // 1 (pad 4)
#define F_BHI    1940         // drift hi: 32 groups x 32 lanes x uint2 (8KB)
#define F_BLO    3988         // drift lo: 8KB
#define F_STAGE  6036         // 128 rows x pitch 68
#define ST_PITCH 68
#define F_TOTAL  (F_STAGE + 128*ST_PITCH)
#define SMEM_BYTES (F_TOTAL*4)        // 58960 B

__device__ float g_noise[NDEPTH*64];
// one-time fragment tables in global (built by prep_kernel, read once per CTA)
__device__ uint2 g_tWDhi[32*32], g_tWDlo[32*32];   // W_down,  g = kt*8 + nt
__device__ uint2 g_tDRhi[32*32], g_tDRlo[32*32];   // W_drift, g = kt*8 + nt
__device__ uint2 g_tW1hi[52*32], g_tW1lo[52*32];   // W1,      g = kt*13 + nt

// ---------------- fp16 pack/split helpers ----------------
__device__ __forceinline__ uint32_t pkh(float e0, float e1) {
    uint32_t r;
    asm("cvt.rn.f16x2.f32 %0, %1, %2;" : "=r"(r) : "f"(e1), "f"(e0));
    return r;
}
__device__ __forceinline__ float h_lo(uint32_t p) {
    __half2 h = *(__half2*)&p; return __low2float(h);
}
__device__ __forceinline__ float h_hi(uint32_t p) {
    __half2 h = *(__half2*)&p; return __high2float(h);
}
__device__ __forceinline__ void split2(float v0, float v1, uint32_t& hi, uint32_t& lo) {
    hi = pkh(v0, v1);
    lo = pkh(v0 - h_lo(hi), v1 - h_hi(hi));
}

__device__ __forceinline__ void mma16816(float* c,
                                         uint32_t a0, uint32_t a1, uint32_t a2, uint32_t a3,
                                         uint32_t b0, uint32_t b1) {
    asm volatile(
        "mma.sync.aligned.m16n8k16.row.col.f32.f16.f16.f32 "
        "{%0,%1,%2,%3}, {%4,%5,%6,%7}, {%8,%9}, {%0,%1,%2,%3};"
        : "+f"(c[0]), "+f"(c[1]), "+f"(c[2]), "+f"(c[3])
        : "r"(a0), "r"(a1), "r"(a2), "r"(a3), "r"(b0), "r"(b1));
}

// ---------------- Lévy noise prologue (fp32 — reference math is fp32) ----------------
__global__ void noise_kernel(const float* __restrict__ u_raw,
                             const float* __restrict__ w_raw) {
    int i = blockIdx.x * blockDim.x + threadIdx.x;
    if (i >= NDEPTH * 64) return;
    float u = u_raw[i];
    float w = w_raw[i];
    float U = 3.14159265358979f * (u - 0.5f);
    float wc = fminf(fmaxf(w, 1e-12f), 1.0f);
    float Wv = fmaxf(-logf(wc), 1e-12f);
    const float inv_a = 1.0f / 1.8f;
    float X = (sinf(1.8f * U) / powf(cosf(U), inv_a))
            * powf(cosf(U - 1.8f * U) / Wv, (1.0f - 1.8f) * inv_a);
    g_noise[i] = fminf(fmaxf(0.1f * X, -10.0f), 10.0f);
}

// ---------------- fragment-table prep (one-time) ----------------
__global__ void prep_kernel(const float* __restrict__ W_down,
                            const float* __restrict__ W_drift,
                            const float* __restrict__ W1) {
    int idx = blockIdx.x * blockDim.x + threadIdx.x;
    int lane = idx & 31, g = idx >> 5;
    int quad = lane >> 2, qt = lane & 3;
    if (idx < 1024) {
        int nt = g & 7, kt = g >> 3;
        int n = quad + 8 * nt;
        int k = 16 * kt + 2 * qt;
        uint32_t h0, l0, h1, l1;
        split2(W_down[k * 64 + n],       W_down[(k + 1) * 64 + n], h0, l0);
        split2(W_down[(k + 8) * 64 + n], W_down[(k + 9) * 64 + n], h1, l1);
        g_tWDhi[idx] = make_uint2(h0, h1);
        g_tWDlo[idx] = make_uint2(l0, l1);
        split2(W_drift[k * 64 + n],       W_drift[(k + 1) * 64 + n], h0, l0);
        split2(W_drift[(k + 8) * 64 + n], W_drift[(k + 9) * 64 + n], h1, l1);
        g_tDRhi[idx] = make_uint2(h0, h1);
        g_tDRlo[idx] = make_uint2(l0, l1);
    }
    if (idx < 1664) {
        int nt = g % 13, kt = g / 13;
        int n = quad + 8 * nt;
        int k = 16 * kt + 2 * qt;
        float w0 = (n < 100) ? W1[k * 100 + n]       : 0.0f;
        float w1 = (n < 100) ? W1[(k + 1) * 100 + n] : 0.0f;
        float w2 = (n < 100) ? W1[(k + 8) * 100 + n] : 0.0f;
        float w3 = (n < 100) ? W1[(k + 9) * 100 + n] : 0.0f;
        uint32_t h0, l0, h1, l1;
        split2(w0, w1, h0, l0);
        split2(w2, w3, h1, l1);
        g_tW1hi[idx] = make_uint2(h0, h1);
        g_tW1lo[idx] = make_uint2(l0, l1);
    }
}

// ---------------- main: 8 warps/CTA, 3 CTAs/SM, warp owns rows 16w..16w+15 ----------------
__global__ void __launch_bounds__(NTHREADS, 3)
sdenet_mma(const float* __restrict__ x,
           const float* __restrict__ b_down,
           const float* __restrict__ b_drift,
           const float* __restrict__ b1,
           const float* __restrict__ W2,
           const float* __restrict__ b2,
           float* __restrict__ out) {
    extern __shared__ float sm[];
    const int tid  = threadIdx.x;
    const int wid  = tid >> 5;
    const int lane = tid & 31;
    const int quad = lane >> 2;
    const int qt   = lane & 3;

    // ---- cooperative loads ----
    for (int i = tid; i < NDEPTH * 64; i += NTHREADS) sm[F_NOISE + i] = g_noise[i];
    if (tid < 64)  { sm[F_BD + tid] = b_down[tid]; sm[F_BDR + tid] = b_drift[tid]; }
    if (tid < 104) {
        sm[F_B1 + tid] = (tid < 100) ? b1[tid] : 0.0f;
        sm[F_W2 + tid] = (tid < 100) ? W2[tid] : 0.0f;
    }
    if (tid == 0) sm[F_B2] = b2[0];
    // drift tables global -> smem (coalesced)
    {
        uint2* th = (uint2*)&sm[F_BHI];
        uint2* tl = (uint2*)&sm[F_BLO];
        for (int i = tid; i < 1024; i += NTHREADS) {
            th[i] = g_tDRhi[i];
            tl[i] = g_tDRlo[i];
        }
    }
    // x tile -> stage (coalesced)
    const float* xb = x + (size_t)blockIdx.x * (TILE_M * 64);
    for (int i = 4 * tid; i < TILE_M * 64; i += 4 * NTHREADS) {
        float4 v = *(const float4*)(xb + i);
        int r = i >> 6, c = i & 63;
        *(float4*)&sm[F_STAGE + r * ST_PITCH + c] = v;
    }
    __syncthreads();

    const int row0 = 16 * wid + quad;

    // ---- A fragments of x (hi/lo) ----
    uint32_t ah[16], al[16];
#pragma unroll
    for (int kt = 0; kt < 4; kt++) {
        int k0 = 16 * kt + 2 * qt;
        const float* r0p = &sm[F_STAGE + row0 * ST_PITCH];
        const float* r1p = &sm[F_STAGE + (row0 + 8) * ST_PITCH];
        split2(r0p[k0],     r0p[k0 + 1], ah[4*kt + 0], al[4*kt + 0]);
        split2(r1p[k0],     r1p[k0 + 1], ah[4*kt + 1], al[4*kt + 1]);
        split2(r0p[k0 + 8], r0p[k0 + 9], ah[4*kt + 2], al[4*kt + 2]);
        split2(r1p[k0 + 8], r1p[k0 + 9], ah[4*kt + 3], al[4*kt + 3]);
    }

    // ---- GEMM1: s = x @ W_down + b_down (3-term fp16; B frags from global table) ----
    float d[8][4];
#pragma unroll
    for (int nt = 0; nt < 8; nt++) {
        int c0 = 8 * nt + 2 * qt;
        float c[4] = { sm[F_BD + c0], sm[F_BD + c0 + 1], sm[F_BD + c0], sm[F_BD + c0 + 1] };
#pragma unroll
        for (int kt = 0; kt < 4; kt++) {
            uint2 bh = g_tWDhi[(kt * 8 + nt) * 32 + lane];
            uint2 bl = g_tWDlo[(kt * 8 + nt) * 32 + lane];
            mma16816(c, ah[4*kt], ah[4*kt+1], ah[4*kt+2], ah[4*kt+3], bh.x, bh.y);
            mma16816(c, al[4*kt], al[4*kt+1], al[4*kt+2], al[4*kt+3], bh.x, bh.y);
            mma16816(c, ah[4*kt], ah[4*kt+1], ah[4*kt+2], ah[4*kt+3], bl.x, bl.y);
        }
        d[nt][0] = c[0]; d[nt][1] = c[1]; d[nt][2] = c[2]; d[nt][3] = c[3];
    }

    // rebuild A fragments from state (full split for MLP precision)
#pragma unroll
    for (int kt = 0; kt < 4; kt++) {
        split2(d[2*kt][0],   d[2*kt][1],   ah[4*kt + 0], al[4*kt + 0]);
        split2(d[2*kt][2],   d[2*kt][3],   ah[4*kt + 1], al[4*kt + 1]);
        split2(d[2*kt+1][0], d[2*kt+1][1], ah[4*kt + 2], al[4*kt + 2]);
        split2(d[2*kt+1][2], d[2*kt+1][3], ah[4*kt + 3], al[4*kt + 3]);
    }

    // ---- diffusion MLP (3-term fp16; B frags from global table) ----
    float p0 = 0.0f, p1 = 0.0f;
#pragma unroll
    for (int nt = 0; nt < 13; nt++) {
        float c[4] = {0.f, 0.f, 0.f, 0.f};
#pragma unroll
        for (int kt = 0; kt < 4; kt++) {
            uint2 bh = g_tW1hi[(kt * 13 + nt) * 32 + lane];
            uint2 bl = g_tW1lo[(kt * 13 + nt) * 32 + lane];
            mma16816(c, ah[4*kt], ah[4*kt+1], ah[4*kt+2], ah[4*kt+3], bh.x, bh.y);
            mma16816(c, al[4*kt], al[4*kt+1], al[4*kt+2], al[4*kt+3], bh.x, bh.y);
            mma16816(c, ah[4*kt], ah[4*kt+1], ah[4*kt+2], ah[4*kt+3], bl.x, bl.y);
        }
        int c0 = 8 * nt + 2 * qt;
        float w20 = sm[F_W2 + c0], w21 = sm[F_W2 + c0 + 1];
        float bb0 = sm[F_B1 + c0], bb1 = sm[F_B1 + c0 + 1];
        p0 += fmaxf(c[0] + bb0, 0.f) * w20 + fmaxf(c[1] + bb1, 0.f) * w21;
        p1 += fmaxf(c[2] + bb0, 0.f) * w20 + fmaxf(c[3] + bb1, 0.f) * w21;
    }
    p0 += __shfl_xor_sync(0xffffffffu, p0, 1);
    p0 += __shfl_xor_sync(0xffffffffu, p0, 2);
    p1 += __shfl_xor_sync(0xffffffffu, p1, 1);
    p1 += __shfl_xor_sync(0xffffffffu, p1, 2);
    const float dtpow = powf(DT, 1.0f / 1.8f);
    const float b2v = sm[F_B2];
    const float scale0 = 0.5f * dtpow / (1.0f + expf(-(p0 + b2v)));
    const float scale1 = 0.5f * dtpow / (1.0f + expf(-(p1 + b2v)));

    // ---- 25 drift steps: single-term A-hi x B-hi, nt-OUTER (c[4] transient only) ----
    // Loop live set: d[32] + ah[16] + ptrs/scales ~10 + transients ~10  => ~72 regs,
    // safely under the (256,3) 85-reg cap — no loop spills.
    const uint2* tbh = (const uint2*)&sm[F_BHI] + lane;
    const uint2* tbl = (const uint2*)&sm[F_BLO] + lane;
    const float* bdrp = &sm[F_BDR + 2 * qt];
    const float* nzp  = &sm[F_NOISE + 2 * qt];
#pragma unroll 1
    for (int st = 0; st < NDEPTH; st++) {
        const float* nz = nzp + st * 64;
#pragma unroll
        for (int nt = 0; nt < 8; nt++) {
            float2 bb = *(const float2*)(bdrp + 8 * nt);
            float c[4] = { bb.x, bb.y, bb.x, bb.y };
#pragma unroll
            for (int kt = 0; kt < 4; kt++) {
                uint2 b = tbh[(kt * 8 + nt) * 32];
                mma16816(c, ah[4*kt], ah[4*kt+1], ah[4*kt+2], ah[4*kt+3], b.x, b.y);
            }
            float2 z = *(const float2*)(nz + 8 * nt);
            d[nt][0] = fmaf(d[nt][0], 1.0f + DT, fmaf(fmaxf(c[0], 0.f), DT, scale0 * z.x));
            d[nt][1] = fmaf(d[nt][1], 1.0f + DT, fmaf(fmaxf(c[1], 0.f), DT, scale0 * z.y));
            d[nt][2] = fmaf(d[nt][2], 1.0f + DT, fmaf(fmaxf(c[2], 0.f), DT, scale1 * z.x));
            d[nt][3] = fmaf(d[nt][3], 1.0f + DT, fmaf(fmaxf(c[3], 0.f), DT, scale1 * z.y));
        }
        // A-hi rebuild: one cvt per fragment
#pragma unroll
        for (int kt = 0; kt < 4; kt++) {
            ah[4*kt + 0] = pkh(d[2*kt][0],   d[2*kt][1]);
            ah[4*kt + 1] = pkh(d[2*kt][2],   d[2*kt][3]);
            ah[4*kt + 2] = pkh(d[2*kt+1][0], d[2*kt+1][1]);
            ah[4*kt + 3] = pkh(d[2*kt+1][2], d[2*kt+1][3]);
        }
    }

    // ---- final drift_out GEMM: full precision (3-term, A fully split) ----
#pragma unroll
    for (int kt = 0; kt < 4; kt++) {
        split2(d[2*kt][0],   d[2*kt][1],   ah[4*kt + 0], al[4*kt + 0]);
        split2(d[2*kt][2],   d[2*kt][3],   ah[4*kt + 1], al[4*kt + 1]);
        split2(d[2*kt+1][0], d[2*kt+1][1], ah[4*kt + 2], al[4*kt + 2]);
        split2(d[2*kt+1][2], d[2*kt+1][3], ah[4*kt + 3], al[4*kt + 3]);
    }
#pragma unroll
    for (int nt = 0; nt < 8; nt++) {
        int c0 = 8 * nt + 2 * qt;
        float2 bb = *(const float2*)&sm[F_BDR + c0];
        float c[4] = { bb.x, bb.y, bb.x, bb.y };
#pragma unroll
        for (int kt = 0; kt < 4; kt++) {
            uint2 b = tbh[(kt * 8 + nt) * 32];
            uint2 l = tbl[(kt * 8 + nt) * 32];
            mma16816(c, ah[4*kt], ah[4*kt+1], ah[4*kt+2], ah[4*kt+3], b.x, b.y);
            mma16816(c, al[4*kt], al[4*kt+1], al[4*kt+2], al[4*kt+3], b.x, b.y);
            mma16816(c, ah[4*kt], ah[4*kt+1], ah[4*kt+2], ah[4*kt+3], l.x, l.y);
        }
        sm[F_STAGE + row0 * ST_PITCH + c0]           = fmaxf(c[0], 0.f) + d[nt][0];
        sm[F_STAGE + row0 * ST_PITCH + c0 + 1]       = fmaxf(c[1], 0.f) + d[nt][1];
        sm[F_STAGE + (row0 + 8) * ST_PITCH + c0]     = fmaxf(c[2], 0.f) + d[nt][2];
        sm[F_STAGE + (row0 + 8) * ST_PITCH + c0 + 1] = fmaxf(c[3], 0.f) + d[nt][3];
    }

    // ---- write drift_out (coalesced via stage) ----
    __syncthreads();
    float* o0 = out + (size_t)blockIdx.x * (TILE_M * 64);
    for (int i = 4 * tid; i < TILE_M * 64; i += 4 * NTHREADS) {
        int r = i >> 6, c = i & 63;
        *(float4*)(o0 + i) = *(const float4*)&sm[F_STAGE + r * ST_PITCH + c];
    }
    __syncthreads();

    // ---- stage + write final state ----
#pragma unroll
    for (int nt = 0; nt < 8; nt++) {
        int c0 = 8 * nt + 2 * qt;
        sm[F_STAGE + row0 * ST_PITCH + c0]           = d[nt][0];
        sm[F_STAGE + row0 * ST_PITCH + c0 + 1]       = d[nt][1];
        sm[F_STAGE + (row0 + 8) * ST_PITCH + c0]     = d[nt][2];
        sm[F_STAGE + (row0 + 8) * ST_PITCH + c0 + 1] = d[nt][3];
    }
    __syncthreads();
    float* o1 = out + (size_t)NBATCH * 64 + (size_t)blockIdx.x * (TILE_M * 64);
    for (int i = 4 * tid; i < TILE_M * 64; i += 4 * NTHREADS) {
        int r = i >> 6, c = i & 63;
        *(float4*)(o1 + i) = *(const float4*)&sm[F_STAGE + r * ST_PITCH + c];
    }
}

extern "C" void kernel_launch(void* const* d_in, const int* in_sizes, int n_in,
                              void* d_out, int out_size) {
    const float* x       = (const float*)d_in[0];
    const float* u_raw   = (const float*)d_in[1];
    const float* w_raw   = (const float*)d_in[2];
    const float* W_down  = (const float*)d_in[3];
    const float* b_down  = (const float*)d_in[4];
    const float* W_drift = (const float*)d_in[5];
    const float* b_drift = (const float*)d_in[6];
    const float* W1      = (const float*)d_in[7];
    const float* b1      = (const float*)d_in[8];
    const float* W2      = (const float*)d_in[9];
    const float* b2      = (const float*)d_in[10];
    float* out = (float*)d_out;

    noise_kernel<<<(NDEPTH * 64 + 255) / 256, 256>>>(u_raw, w_raw);
    prep_kernel<<<7, 256>>>(W_down, W_drift, W1);

    cudaFuncSetAttribute(sdenet_mma,
                         cudaFuncAttributeMaxDynamicSharedMemorySize, SMEM_BYTES);
    sdenet_mma<<<NBATCH / TILE_M, NTHREADS, SMEM_BYTES>>>(
        x, b_down, b_drift, b1, W2, b2, out);
}

// round 15
// speedup vs baseline: 1.4968x; 1.1265x over previous
#include <cuda_runtime.h>
#include <cuda_fp16.h>
#include <math.h>
#include <stdint.h>

#define NDEPTH 25
#define DT     (1.0f/25.0f)
#define NBATCH 262144
#define TILE_M 128
#define NTHREADS 256

// ---------------- smem float-index offsets (~42.6KB per CTA, 2 CTAs/SM) ----------------
#define F_NOISE  0            // 25x64
#define F_BD     1600         // 64
#define F_BDR    1664         // 64
#define F_B1     1728         // 104
#define F_W2     1832         // 104
#define F_B2     1936         // 1 (pad 4)
#define F_STAGE  1940         // 128 rows x pitch 68
#define ST_PITCH 68
#define F_TOTAL  (F_STAGE + 128*ST_PITCH)
#define SMEM_BYTES (F_TOTAL*4)        // 42576 B

__device__ float g_noise[NDEPTH*64];
// one-time fragment tables in global (built by prep_kernel; L2-resident)
__device__ uint2 g_tWDhi[32*32], g_tWDlo[32*32];   // W_down,  g = kt*8 + nt
__device__ uint2 g_tDRhi[32*32], g_tDRlo[32*32];   // W_drift, g = kt*8 + nt
__device__ uint2 g_tW1hi[52*32];                   // W1,      g = kt*13 + nt

// ---------------- fp16 pack/split helpers ----------------
__device__ __forceinline__ uint32_t pkh(float e0, float e1) {
    uint32_t r;
    asm("cvt.rn.f16x2.f32 %0, %1, %2;" : "=r"(r) : "f"(e1), "f"(e0));
    return r;
}
__device__ __forceinline__ float h_lo(uint32_t p) {
    __half2 h = *(__half2*)&p; return __low2float(h);
}
__device__ __forceinline__ float h_hi(uint32_t p) {
    __half2 h = *(__half2*)&p; return __high2float(h);
}
__device__ __forceinline__ void split2(float v0, float v1, uint32_t& hi, uint32_t& lo) {
    hi = pkh(v0, v1);
    lo = pkh(v0 - h_lo(hi), v1 - h_hi(hi));
}

__device__ __forceinline__ void mma16816(float* c,
                                         uint32_t a0, uint32_t a1, uint32_t a2, uint32_t a3,
                                         uint32_t b0, uint32_t b1) {
    asm volatile(
        "mma.sync.aligned.m16n8k16.row.col.f32.f16.f16.f32 "
        "{%0,%1,%2,%3}, {%4,%5,%6,%7}, {%8,%9}, {%0,%1,%2,%3};"
        : "+f"(c[0]), "+f"(c[1]), "+f"(c[2]), "+f"(c[3])
        : "r"(a0), "r"(a1), "r"(a2), "r"(a3), "r"(b0), "r"(b1));
}

// ---------------- Lévy noise prologue (fp32) ----------------
__global__ void noise_kernel(const float* __restrict__ u_raw,
                             const float* __restrict__ w_raw) {
    int i = blockIdx.x * blockDim.x + threadIdx.x;
    if (i >= NDEPTH * 64) return;
    float u = u_raw[i];
    float w = w_raw[i];
    float U = 3.14159265358979f * (u - 0.5f);
    float wc = fminf(fmaxf(w, 1e-12f), 1.0f);
    float Wv = fmaxf(-logf(wc), 1e-12f);
    const float inv_a = 1.0f / 1.8f;
    float X = (sinf(1.8f * U) / powf(cosf(U), inv_a))
            * powf(cosf(U - 1.8f * U) / Wv, (1.0f - 1.8f) * inv_a);
    g_noise[i] = fminf(fmaxf(0.1f * X, -10.0f), 10.0f);
}

// ---------------- fragment-table prep (one-time) ----------------
__global__ void prep_kernel(const float* __restrict__ W_down,
                            const float* __restrict__ W_drift,
                            const float* __restrict__ W1) {
    int idx = blockIdx.x * blockDim.x + threadIdx.x;
    int lane = idx & 31, g = idx >> 5;
    int quad = lane >> 2, qt = lane & 3;
    if (idx < 1024) {
        int nt = g & 7, kt = g >> 3;
        int n = quad + 8 * nt;
        int k = 16 * kt + 2 * qt;
        uint32_t h0, l0, h1, l1;
        split2(W_down[k * 64 + n],       W_down[(k + 1) * 64 + n], h0, l0);
        split2(W_down[(k + 8) * 64 + n], W_down[(k + 9) * 64 + n], h1, l1);
        g_tWDhi[idx] = make_uint2(h0, h1);
        g_tWDlo[idx] = make_uint2(l0, l1);
        split2(W_drift[k * 64 + n],       W_drift[(k + 1) * 64 + n], h0, l0);
        split2(W_drift[(k + 8) * 64 + n], W_drift[(k + 9) * 64 + n], h1, l1);
        g_tDRhi[idx] = make_uint2(h0, h1);
        g_tDRlo[idx] = make_uint2(l0, l1);
    }
    if (idx < 1664) {
        int nt = g % 13, kt = g / 13;
        int n = quad + 8 * nt;
        int k = 16 * kt + 2 * qt;
        float w0 = (n < 100) ? W1[k * 100 + n]       : 0.0f;
        float w1 = (n < 100) ? W1[(k + 1) * 100 + n] : 0.0f;
        float w2 = (n < 100) ? W1[(k + 8) * 100 + n] : 0.0f;
        float w3 = (n < 100) ? W1[(k + 9) * 100 + n] : 0.0f;
        g_tW1hi[idx] = make_uint2(pkh(w0, w1), pkh(w2, w3));
    }
}

// ---------------- main: 8 warps/CTA, 2 CTAs/SM, B-hi fragments in registers ----------------
__global__ void __launch_bounds__(NTHREADS, 2)
sdenet_mma(const float* __restrict__ x,
           const float* __restrict__ b_down,
           const float* __restrict__ b_drift,
           const float* __restrict__ b1,
           const float* __restrict__ W2,
           const float* __restrict__ b2,
           float* __restrict__ out) {
    extern __shared__ float sm[];
    const int tid  = threadIdx.x;
    const int wid  = tid >> 5;
    const int lane = tid & 31;
    const int quad = lane >> 2;
    const int qt   = lane & 3;

    // ---- cooperative loads ----
    for (int i = tid; i < NDEPTH * 64; i += NTHREADS) sm[F_NOISE + i] = g_noise[i];
    if (tid < 64)  { sm[F_BD + tid] = b_down[tid]; sm[F_BDR + tid] = b_drift[tid]; }
    if (tid < 104) {
        sm[F_B1 + tid] = (tid < 100) ? b1[tid] : 0.0f;
        sm[F_W2 + tid] = (tid < 100) ? W2[tid] : 0.0f;
    }
    if (tid == 0) sm[F_B2] = b2[0];
    // x tile -> stage (coalesced)
    const float* xb = x + (size_t)blockIdx.x * (TILE_M * 64);
    for (int i = 4 * tid; i < TILE_M * 64; i += 4 * NTHREADS) {
        float4 v = *(const float4*)(xb + i);
        int r = i >> 6, c = i & 63;
        *(float4*)&sm[F_STAGE + r * ST_PITCH + c] = v;
    }
    __syncthreads();

    const int row0 = 16 * wid + quad;

    // ---- A fragments of x (hi/lo) ----
    uint32_t ah[16], al[16];
#pragma unroll
    for (int kt = 0; kt < 4; kt++) {
        int k0 = 16 * kt + 2 * qt;
        const float* r0p = &sm[F_STAGE + row0 * ST_PITCH];
        const float* r1p = &sm[F_STAGE + (row0 + 8) * ST_PITCH];
        split2(r0p[k0],     r0p[k0 + 1], ah[4*kt + 0], al[4*kt + 0]);
        split2(r1p[k0],     r1p[k0 + 1], ah[4*kt + 1], al[4*kt + 1]);
        split2(r0p[k0 + 8], r0p[k0 + 9], ah[4*kt + 2], al[4*kt + 2]);
        split2(r1p[k0 + 8], r1p[k0 + 9], ah[4*kt + 3], al[4*kt + 3]);
    }

    // ---- GEMM1: s = x @ W_down + b_down (3-term fp16; B frags from global table) ----
    float d[8][4];
#pragma unroll
    for (int nt = 0; nt < 8; nt++) {
        int c0 = 8 * nt + 2 * qt;
        float c[4] = { sm[F_BD + c0], sm[F_BD + c0 + 1], sm[F_BD + c0], sm[F_BD + c0 + 1] };
#pragma unroll
        for (int kt = 0; kt < 4; kt++) {
            uint2 bh = g_tWDhi[(kt * 8 + nt) * 32 + lane];
            uint2 bl = g_tWDlo[(kt * 8 + nt) * 32 + lane];
            mma16816(c, ah[4*kt], ah[4*kt+1], ah[4*kt+2], ah[4*kt+3], bh.x, bh.y);
            mma16816(c, al[4*kt], al[4*kt+1], al[4*kt+2], al[4*kt+3], bh.x, bh.y);
            mma16816(c, ah[4*kt], ah[4*kt+1], ah[4*kt+2], ah[4*kt+3], bl.x, bl.y);
        }
        d[nt][0] = c[0]; d[nt][1] = c[1]; d[nt][2] = c[2]; d[nt][3] = c[3];
    }

    // A-hi rebuild only (MLP is single-term now)
#pragma unroll
    for (int kt = 0; kt < 4; kt++) {
        ah[4*kt + 0] = pkh(d[2*kt][0],   d[2*kt][1]);
        ah[4*kt + 1] = pkh(d[2*kt][2],   d[2*kt][3]);
        ah[4*kt + 2] = pkh(d[2*kt+1][0], d[2*kt+1][1]);
        ah[4*kt + 3] = pkh(d[2*kt+1][2], d[2*kt+1][3]);
    }

    // ---- diffusion MLP (single-term fp16 — scale tolerance is loose) ----
    float p0 = 0.0f, p1 = 0.0f;
#pragma unroll
    for (int nt = 0; nt < 13; nt++) {
        float c[4] = {0.f, 0.f, 0.f, 0.f};
#pragma unroll
        for (int kt = 0; kt < 4; kt++) {
            uint2 bh = g_tW1hi[(kt * 13 + nt) * 32 + lane];
            mma16816(c, ah[4*kt], ah[4*kt+1], ah[4*kt+2], ah[4*kt+3], bh.x, bh.y);
        }
        int c0 = 8 * nt + 2 * qt;
        float w20 = sm[F_W2 + c0], w21 = sm[F_W2 + c0 + 1];
        float bb0 = sm[F_B1 + c0], bb1 = sm[F_B1 + c0 + 1];
        p0 += fmaxf(c[0] + bb0, 0.f) * w20 + fmaxf(c[1] + bb1, 0.f) * w21;
        p1 += fmaxf(c[2] + bb0, 0.f) * w20 + fmaxf(c[3] + bb1, 0.f) * w21;
    }
    p0 += __shfl_xor_sync(0xffffffffu, p0, 1);
    p0 += __shfl_xor_sync(0xffffffffu, p0, 2);
    p1 += __shfl_xor_sync(0xffffffffu, p1, 1);
    p1 += __shfl_xor_sync(0xffffffffu, p1, 2);
    const float dtpow = powf(DT, 1.0f / 1.8f);
    const float b2v = sm[F_B2];
    const float scale0 = 0.5f * dtpow / (1.0f + expf(-(p0 + b2v)));
    const float scale1 = 0.5f * dtpow / (1.0f + expf(-(p1 + b2v)));

    // ---- pin W_drift hi fragments in REGISTERS (64 regs), used by loop + final ----
    uint2 bh[32];
#pragma unroll
    for (int g = 0; g < 32; g++) bh[g] = g_tDRhi[g * 32 + lane];

    // ---- 25 drift steps: single-term A-hi x B-hi, ALL MMA operands in registers ----
    // Loop smem traffic: only bias + noise float2 per nt (16 LDS.64/step).
    const float* bdrp = &sm[F_BDR + 2 * qt];
    const float* nzp  = &sm[F_NOISE + 2 * qt];
#pragma unroll 1
    for (int st = 0; st < NDEPTH; st++) {
        const float* nz = nzp + st * 64;
#pragma unroll
        for (int nt = 0; nt < 8; nt++) {
            float2 bb = *(const float2*)(bdrp + 8 * nt);
            float c[4] = { bb.x, bb.y, bb.x, bb.y };
#pragma unroll
            for (int kt = 0; kt < 4; kt++)
                mma16816(c, ah[4*kt], ah[4*kt+1], ah[4*kt+2], ah[4*kt+3],
                         bh[kt * 8 + nt].x, bh[kt * 8 + nt].y);
            float2 z = *(const float2*)(nz + 8 * nt);
            d[nt][0] = fmaf(d[nt][0], 1.0f + DT, fmaf(fmaxf(c[0], 0.f), DT, scale0 * z.x));
            d[nt][1] = fmaf(d[nt][1], 1.0f + DT, fmaf(fmaxf(c[1], 0.f), DT, scale0 * z.y));
            d[nt][2] = fmaf(d[nt][2], 1.0f + DT, fmaf(fmaxf(c[2], 0.f), DT, scale1 * z.x));
            d[nt][3] = fmaf(d[nt][3], 1.0f + DT, fmaf(fmaxf(c[3], 0.f), DT, scale1 * z.y));
        }
        // A-hi rebuild: one cvt per fragment
#pragma unroll
        for (int kt = 0; kt < 4; kt++) {
            ah[4*kt + 0] = pkh(d[2*kt][0],   d[2*kt][1]);
            ah[4*kt + 1] = pkh(d[2*kt][2],   d[2*kt][3]);
            ah[4*kt + 2] = pkh(d[2*kt+1][0], d[2*kt+1][1]);
            ah[4*kt + 3] = pkh(d[2*kt+1][2], d[2*kt+1][3]);
        }
    }

    // ---- final drift_out GEMM: full precision (3-term; bl from global, once) ----
#pragma unroll
    for (int kt = 0; kt < 4; kt++) {
        split2(d[2*kt][0],   d[2*kt][1],   ah[4*kt + 0], al[4*kt + 0]);
        split2(d[2*kt][2],   d[2*kt][3],   ah[4*kt + 1], al[4*kt + 1]);
        split2(d[2*kt+1][0], d[2*kt+1][1], ah[4*kt + 2], al[4*kt + 2]);
        split2(d[2*kt+1][2], d[2*kt+1][3], ah[4*kt + 3], al[4*kt + 3]);
    }
#pragma unroll
    for (int nt = 0; nt < 8; nt++) {
        int c0 = 8 * nt + 2 * qt;
        float2 bb = *(const float2*)&sm[F_BDR + c0];
        float c[4] = { bb.x, bb.y, bb.x, bb.y };
#pragma unroll
        for (int kt = 0; kt < 4; kt++) {
            uint2 b = bh[kt * 8 + nt];
            uint2 l = g_tDRlo[(kt * 8 + nt) * 32 + lane];
            mma16816(c, ah[4*kt], ah[4*kt+1], ah[4*kt+2], ah[4*kt+3], b.x, b.y);
            mma16816(c, al[4*kt], al[4*kt+1], al[4*kt+2], al[4*kt+3], b.x, b.y);
            mma16816(c, ah[4*kt], ah[4*kt+1], ah[4*kt+2], ah[4*kt+3], l.x, l.y);
        }
        sm[F_STAGE + row0 * ST_PITCH + c0]           = fmaxf(c[0], 0.f) + d[nt][0];
        sm[F_STAGE + row0 * ST_PITCH + c0 + 1]       = fmaxf(c[1], 0.f) + d[nt][1];
        sm[F_STAGE + (row0 + 8) * ST_PITCH + c0]     = fmaxf(c[2], 0.f) + d[nt][2];
        sm[F_STAGE + (row0 + 8) * ST_PITCH + c0 + 1] = fmaxf(c[3], 0.f) + d[nt][3];
    }

    // ---- write drift_out (coalesced via stage) ----
    __syncthreads();
    float* o0 = out + (size_t)blockIdx.x * (TILE_M * 64);
    for (int i = 4 * tid; i < TILE_M * 64; i += 4 * NTHREADS) {
        int r = i >> 6, c = i & 63;
        *(float4*)(o0 + i) = *(const float4*)&sm[F_STAGE + r * ST_PITCH + c];
    }
    __syncthreads();

    // ---- stage + write final state ----
#pragma unroll
    for (int nt = 0; nt < 8; nt++) {
        int c0 = 8 * nt + 2 * qt;
        sm[F_STAGE + row0 * ST_PITCH + c0]           = d[nt][0];
        sm[F_STAGE + row0 * ST_PITCH + c0 + 1]       = d[nt][1];
        sm[F_STAGE + (row0 + 8) * ST_PITCH + c0]     = d[nt][2];
        sm[F_STAGE + (row0 + 8) * ST_PITCH + c0 + 1] = d[nt][3];
    }
    __syncthreads();
    float* o1 = out + (size_t)NBATCH * 64 + (size_t)blockIdx.x * (TILE_M * 64);
    for (int i = 4 * tid; i < TILE_M * 64; i += 4 * NTHREADS) {
        int r = i >> 6, c = i & 63;
        *(float4*)(o1 + i) = *(const float4*)&sm[F_STAGE + r * ST_PITCH + c];
    }
}

extern "C" void kernel_launch(void* const* d_in, const int* in_sizes, int n_in,
                              void* d_out, int out_size) {
    const float* x       = (const float*)d_in[0];
    const float* u_raw   = (const float*)d_in[1];
    const float* w_raw   = (const float*)d_in[2];
    const float* W_down  = (const float*)d_in[3];
    const float* b_down  = (const float*)d_in[4];
    const float* W_drift = (const float*)d_in[5];
    const float* b_drift = (const float*)d_in[6];
    const float* W1      = (const float*)d_in[7];
    const float* b1      = (const float*)d_in[8];
    const float* W2      = (const float*)d_in[9];
    const float* b2      = (const float*)d_in[10];
    float* out = (float*)d_out;

    noise_kernel<<<(NDEPTH * 64 + 255) / 256, 256>>>(u_raw, w_raw);
    prep_kernel<<<7, 256>>>(W_down, W_drift, W1);

    cudaFuncSetAttribute(sdenet_mma,
                         cudaFuncAttributeMaxDynamicSharedMemorySize, SMEM_BYTES);
    sdenet_mma<<<NBATCH / TILE_M, NTHREADS, SMEM_BYTES>>>(
        x, b_down, b_drift, b1, W2, b2, out);
}